// round 14
// baseline (speedup 1.0000x reference)
#include <cuda_runtime.h>
#include <cuda_bf16.h>
#include <math.h>
#include <stdint.h>

// Problem constants
#define BATCH 2
#define SEQ   1024
#define TKN   2048      // BATCH*SEQ
#define HIDN  2048
#define NHEADS 32
#define KVN   512       // G*HD = 8*64
#define HD    64

// Scratch (static device arrays: no allocation allowed)
__device__ __nv_bfloat16 g_xb [TKN * HIDN];
__device__ __nv_bfloat16 g_WqT[HIDN * HIDN];
__device__ __nv_bfloat16 g_WkT[KVN * HIDN];
__device__ __nv_bfloat16 g_WvT[KVN * HIDN];
__device__ __nv_bfloat16 g_WoT[HIDN * HIDN];
__device__ __nv_bfloat16 g_Qb [TKN * HIDN];
__device__ __nv_bfloat16 g_Kb [TKN * KVN];
__device__ __nv_bfloat16 g_Vb [TKN * KVN];
__device__ __nv_bfloat16 g_Ab [TKN * HIDN];

// ---------------------------------------------------------------------------
// helpers
// ---------------------------------------------------------------------------
__device__ __forceinline__ uint32_t bf2(float lo, float hi) {
    uint32_t r;
    asm("cvt.rn.bf16x2.f32 %0, %1, %2;" : "=r"(r) : "f"(hi), "f"(lo));
    return r;
}
__device__ __forceinline__ float2 ubf2(uint32_t w) {
    __nv_bfloat162 h = *reinterpret_cast<__nv_bfloat162*>(&w);
    return __bfloat1622float2(h);
}
__device__ __forceinline__ uint32_t s2u(const void* p) {
    return (uint32_t)__cvta_generic_to_shared(p);
}

// mma.sync m16n8k16 bf16: D = A*B + D (fp32 accum)
__device__ __forceinline__ void mma16(float d[4], const uint32_t* a, const uint32_t* b) {
    asm volatile(
        "mma.sync.aligned.m16n8k16.row.col.f32.bf16.bf16.f32 "
        "{%0,%1,%2,%3}, {%4,%5,%6,%7}, {%8,%9}, {%0,%1,%2,%3};\n"
        : "+f"(d[0]), "+f"(d[1]), "+f"(d[2]), "+f"(d[3])
        : "r"(a[0]), "r"(a[1]), "r"(a[2]), "r"(a[3]), "r"(b[0]), "r"(b[1]));
}

__device__ __forceinline__ float fast_exp2(float x) {
    x = fmaxf(x, -125.0f);
    int n = __float2int_rn(x);
    float f = x - (float)n;
    float p = 1.5403530393381609e-4f;
    p = fmaf(p, f, 1.3333558146428443e-3f);
    p = fmaf(p, f, 9.6181291076284772e-3f);
    p = fmaf(p, f, 5.5504108664821580e-2f);
    p = fmaf(p, f, 2.4022650695910071e-1f);
    p = fmaf(p, f, 6.9314718055994531e-1f);
    p = fmaf(p, f, 1.0f);
    return __int_as_float((n + 127) << 23) * p;
}

__device__ __forceinline__ void cpa16(uint32_t dst, const void* src) {
    asm volatile("cp.async.cg.shared.global [%0], [%1], 16;\n" :: "r"(dst), "l"(src));
}

// ---------------------------------------------------------------------------
// Prep kernels: x fp32 -> bf16; W[K,N] fp32 -> WT[N,K] bf16
// ---------------------------------------------------------------------------
__global__ __launch_bounds__(256) void cvt_x_kernel(const float* __restrict__ x,
                                                    __nv_bfloat16* __restrict__ xb)
{
    const size_t i = ((size_t)blockIdx.x * 256 + threadIdx.x) * 8;
    float4 a = *(const float4*)&x[i];
    float4 b = *(const float4*)&x[i + 4];
    uint4 o;
    o.x = bf2(a.x, a.y); o.y = bf2(a.z, a.w);
    o.z = bf2(b.x, b.y); o.w = bf2(b.z, b.w);
    *(uint4*)&xb[i] = o;
}

__global__ __launch_bounds__(256) void transpose_w_kernel(
    const float* __restrict__ W, __nv_bfloat16* __restrict__ WT, int K, int N)
{
    __shared__ unsigned short t[64][66];
    const int n0 = blockIdx.x * 64, k0 = blockIdx.y * 64;
    const int r = threadIdx.x >> 4, c4 = (threadIdx.x & 15) * 4;
    #pragma unroll
    for (int j = 0; j < 4; j++) {
        const int kk = r + j * 16;
        float4 v = *(const float4*)&W[(size_t)(k0 + kk) * N + n0 + c4];
        uint32_t p0 = bf2(v.x, v.y), p1 = bf2(v.z, v.w);
        t[kk][c4]     = (unsigned short)(p0 & 0xFFFF);
        t[kk][c4 + 1] = (unsigned short)(p0 >> 16);
        t[kk][c4 + 2] = (unsigned short)(p1 & 0xFFFF);
        t[kk][c4 + 3] = (unsigned short)(p1 >> 16);
    }
    __syncthreads();
    #pragma unroll
    for (int j = 0; j < 4; j++) {
        const int nn = r + j * 16;
        uint32_t u0 = (uint32_t)t[c4][nn]     | ((uint32_t)t[c4 + 1][nn] << 16);
        uint32_t u1 = (uint32_t)t[c4 + 2][nn] | ((uint32_t)t[c4 + 3][nn] << 16);
        *(uint2*)&WT[(size_t)(n0 + nn) * K + k0 + c4] = make_uint2(u0, u1);
    }
}

// ---------------------------------------------------------------------------
// NT bf16 GEMM core (R13 proven): C[128,128] = A @ WT^T (+bias, +resid).
// ---------------------------------------------------------------------------
#define GSTR 36               // u32 row stride (32 data + 4 pad) = 144 B
#define GBUF (128 * GSTR)     // u32 per operand buffer (18432 B)
#define G_SMEM (4 * GBUF * 4) // 73728 B

template <bool OUT_BF16>
__device__ __forceinline__ void gemm_nt_core(
    const __nv_bfloat16* __restrict__ Ag, const __nv_bfloat16* __restrict__ Bt,
    const float* __restrict__ bias, void* __restrict__ Cout,
    const float* __restrict__ resid, int Ncols, int mb, int nb)
{
    extern __shared__ __align__(16) uint32_t sh[];
    uint32_t* As = sh;               // [2][GBUF]
    uint32_t* Bs = sh + 2 * GBUF;    // [2][GBUF]

    const int tid = threadIdx.x, lane = tid & 31, warp = tid >> 5;
    const int wm = warp >> 2, wn = warp & 3;
    const int fr = lane >> 2, fc = lane & 3;

    const int lrow = tid >> 1, lhalf = (tid & 1) * 64;
    const uint32_t aDst = s2u(As) + lrow * 144 + lhalf;
    const uint32_t bDst = s2u(Bs) + lrow * 144 + lhalf;
    const __nv_bfloat16* aSrc = Ag + (size_t)(mb + lrow) * HIDN + lhalf / 2;
    const __nv_bfloat16* bSrc = Bt + (size_t)(nb + lrow) * HIDN + lhalf / 2;

    float acc[4][4][4];
    #pragma unroll
    for (int i = 0; i < 4; i++)
        #pragma unroll
        for (int j = 0; j < 4; j++)
            #pragma unroll
            for (int q = 0; q < 4; q++) acc[i][j][q] = 0.0f;

    {
        #pragma unroll
        for (int l = 0; l < 4; l++) {
            cpa16(aDst + l * 16, aSrc + l * 8);
            cpa16(bDst + l * 16, bSrc + l * 8);
        }
        asm volatile("cp.async.commit_group;\n");
    }

    const int nCh = HIDN / 64;   // 32
    for (int it = 0; it < nCh; it++) {
        if (it + 1 < nCh) {
            const int buf = (it + 1) & 1;
            const uint32_t aB = aDst + buf * (GBUF * 4);
            const uint32_t bB = bDst + buf * (GBUF * 4);
            const __nv_bfloat16* as = aSrc + (it + 1) * 64;
            const __nv_bfloat16* bs = bSrc + (it + 1) * 64;
            #pragma unroll
            for (int l = 0; l < 4; l++) {
                cpa16(aB + l * 16, as + l * 8);
                cpa16(bB + l * 16, bs + l * 8);
            }
            asm volatile("cp.async.commit_group;\n");
            asm volatile("cp.async.wait_group 1;\n");
        } else {
            asm volatile("cp.async.wait_group 0;\n");
        }
        __syncthreads();

        const int base = (it & 1) * GBUF;
        #pragma unroll
        for (int ks = 0; ks < 4; ks++) {
            const int kb = ks * 8 + fc;
            uint32_t a[4][4], b[4][2];
            #pragma unroll
            for (int mt = 0; mt < 4; mt++) {
                const int row = base + (wm * 64 + mt * 16 + fr) * GSTR;
                a[mt][0] = As[row + kb];
                a[mt][1] = As[row + 8 * GSTR + kb];
                a[mt][2] = As[row + kb + 4];
                a[mt][3] = As[row + 8 * GSTR + kb + 4];
            }
            #pragma unroll
            for (int nt = 0; nt < 4; nt++) {
                const int row = base + (wn * 32 + nt * 8 + fr) * GSTR;
                b[nt][0] = Bs[row + kb];
                b[nt][1] = Bs[row + kb + 4];
            }
            #pragma unroll
            for (int mt = 0; mt < 4; mt++)
                #pragma unroll
                for (int nt = 0; nt < 4; nt++)
                    mma16(acc[mt][nt], a[mt], b[nt]);
        }
        __syncthreads();
    }

    const int r0 = mb + wm * 64 + fr;
    const int c0 = nb + wn * 32 + fc * 2;
    #pragma unroll
    for (int mt = 0; mt < 4; mt++) {
        #pragma unroll
        for (int nt = 0; nt < 4; nt++) {
            const int r = r0 + mt * 16;
            const int c = c0 + nt * 8;
            const float bx = bias[c], by = bias[c + 1];
            if (OUT_BF16) {
                __nv_bfloat16* C = (__nv_bfloat16*)Cout;
                *(uint32_t*)&C[(size_t)r * Ncols + c] =
                    bf2(acc[mt][nt][0] + bx, acc[mt][nt][1] + by);
                *(uint32_t*)&C[(size_t)(r + 8) * Ncols + c] =
                    bf2(acc[mt][nt][2] + bx, acc[mt][nt][3] + by);
            } else {
                float* C = (float*)Cout;
                const float2 u0 = *(const float2*)&resid[(size_t)r * Ncols + c];
                const float2 u1 = *(const float2*)&resid[(size_t)(r + 8) * Ncols + c];
                *(float2*)&C[(size_t)r * Ncols + c] =
                    make_float2(acc[mt][nt][0] + bx + u0.x, acc[mt][nt][1] + by + u0.y);
                *(float2*)&C[(size_t)(r + 8) * Ncols + c] =
                    make_float2(acc[mt][nt][2] + bx + u1.x, acc[mt][nt][3] + by + u1.y);
            }
        }
    }
}

// Fused Q/K/V projection: blockIdx.x [0,16)->Q, [16,20)->K, [20,24)->V.
__global__ __launch_bounds__(256, 2) void qkv_gemm_kernel(
    const __nv_bfloat16* __restrict__ xb,
    const __nv_bfloat16* __restrict__ WqT, const float* __restrict__ bq, __nv_bfloat16* __restrict__ Qb,
    const __nv_bfloat16* __restrict__ WkT, const float* __restrict__ bk, __nv_bfloat16* __restrict__ Kb,
    const __nv_bfloat16* __restrict__ WvT, const float* __restrict__ bv, __nv_bfloat16* __restrict__ Vb)
{
    const int bx = blockIdx.x, mrow = blockIdx.y * 128;
    if (bx < 16)
        gemm_nt_core<true>(xb, WqT, bq, Qb, nullptr, HIDN, mrow, bx * 128);
    else if (bx < 20)
        gemm_nt_core<true>(xb, WkT, bk, Kb, nullptr, KVN, mrow, (bx - 16) * 128);
    else
        gemm_nt_core<true>(xb, WvT, bv, Vb, nullptr, KVN, mrow, (bx - 20) * 128);
}

// O projection: fp32 out + bias + residual.
__global__ __launch_bounds__(256, 2) void o_gemm_kernel(
    const __nv_bfloat16* __restrict__ Ab, const __nv_bfloat16* __restrict__ WoT,
    const float* __restrict__ bo, float* __restrict__ out,
    const float* __restrict__ resid)
{
    gemm_nt_core<false>(Ab, WoT, bo, out, resid, HIDN,
                        blockIdx.y * 128, blockIdx.x * 128);
}

// ---------------------------------------------------------------------------
// Fused flash attention v2: warp-row ownership end to end.
// block = (b,h,128 q rows); warp owns 16 rows x all 128 keys.
// Online-softmax state (m,l) in registers; 2 syncthreads + 1 syncwarp per tile.
// Vt stored transposed [d][keypair] -> PV B-frags are single-u32 LDS.
// ---------------------------------------------------------------------------
#define FQ_STR 36   // Qs/Ks u32 row stride
#define FP_STR 68   // Ps  u32 row stride
#define VT_STR 68   // Vt  u32 row stride (keypairs)

#define FA_QS   0
#define FA_KS   (128 * FQ_STR)               // 4608
#define FA_VT   (2 * 128 * FQ_STR)           // 9216
#define FA_PS   (FA_VT + 64 * VT_STR)        // 13568
#define FA_U32S (FA_PS + 128 * FP_STR)       // 22272
#define FA_SMEM (FA_U32S * 4)                // 89088 B

__global__ __launch_bounds__(256, 2) void fa_kernel(
    const __nv_bfloat16* __restrict__ Q, const __nv_bfloat16* __restrict__ K,
    const __nv_bfloat16* __restrict__ V, const float* __restrict__ mask,
    __nv_bfloat16* __restrict__ Aout)
{
    extern __shared__ uint32_t shu[];
    uint32_t* Qs = shu + FA_QS;
    uint32_t* Ks = shu + FA_KS;
    uint32_t* Vt = shu + FA_VT;
    uint32_t* Ps = shu + FA_PS;
    unsigned short* Vt16 = (unsigned short*)Vt;

    const int tid = threadIdx.x, lane = tid & 31, warp = tid >> 5;
    const int z = blockIdx.y, b = z >> 5, h = z & 31, g = h >> 2;
    const int q0 = blockIdx.x * 128;
    const size_t tb = (size_t)b * SEQ;
    const float* mbase = mask + (size_t)b * SEQ * SEQ;

    const int fr = lane >> 2, fc = lane & 3;

    // load Q tile (bf16), prescale by (1/8)*log2(e)
    const float qsc = 0.125f * 1.4426950408889634f;
    {
        const int r = tid >> 4, c = (tid & 15) * 4;
        const uint32_t* qp = (const uint32_t*)Q;
        #pragma unroll
        for (int p = 0; p < 8; p++) {
            const int row = r + p * 16;
            const size_t w = ((tb + q0 + row) * HIDN + h * 64 + c) >> 1;
            float2 f0 = ubf2(qp[w]), f1 = ubf2(qp[w + 1]);
            Qs[row * FQ_STR + (c >> 1)]     = bf2(f0.x * qsc, f0.y * qsc);
            Qs[row * FQ_STR + (c >> 1) + 1] = bf2(f1.x * qsc, f1.y * qsc);
        }
    }

    // register-resident online softmax state (rows warp*16+fr, +8+fr)
    float rm0 = -1e30f, rm1 = -1e30f, rl0 = 0.0f, rl1 = 0.0f;

    float acc_o[8][4];
    #pragma unroll
    for (int i = 0; i < 8; i++)
        #pragma unroll
        for (int q = 0; q < 4; q++) acc_o[i][q] = 0.0f;

    const int arow = (warp * 16 + fr) * FQ_STR;
    const int prow0 = (warp * 16 + fr) * FP_STR;
    const int prow1 = prow0 + 8 * FP_STR;

    for (int t = 0; t < 8; t++) {
        __syncthreads();   // all warps done reading Ks/Vt of prev tile
        {
            const int r = tid >> 4, c = (tid & 15) * 4;
            const uint32_t* kp = (const uint32_t*)K;
            const uint32_t* vp = (const uint32_t*)V;
            #pragma unroll
            for (int p = 0; p < 8; p++) {
                const int row = r + p * 16;
                const size_t w = ((tb + t * 128 + row) * KVN + g * 64 + c) >> 1;
                Ks[row * FQ_STR + (c >> 1)]     = kp[w];
                Ks[row * FQ_STR + (c >> 1) + 1] = kp[w + 1];
                const uint32_t v0 = vp[w], v1 = vp[w + 1];
                Vt16[(c + 0) * (2 * VT_STR) + row] = (unsigned short)(v0 & 0xFFFF);
                Vt16[(c + 1) * (2 * VT_STR) + row] = (unsigned short)(v0 >> 16);
                Vt16[(c + 2) * (2 * VT_STR) + row] = (unsigned short)(v1 & 0xFFFF);
                Vt16[(c + 3) * (2 * VT_STR) + row] = (unsigned short)(v1 >> 16);
            }
        }
        __syncthreads();

        // ---- S = Qs @ Ks^T: warp's 16 rows x 128 keys ----
        float s[16][4];
        #pragma unroll
        for (int i = 0; i < 16; i++)
            #pragma unroll
            for (int q = 0; q < 4; q++) s[i][q] = 0.0f;

        #pragma unroll
        for (int ks = 0; ks < 4; ks++) {
            const int kb = ks * 8 + fc;
            uint32_t a[4];
            a[0] = Qs[arow + kb];
            a[1] = Qs[arow + 8 * FQ_STR + kb];
            a[2] = Qs[arow + kb + 4];
            a[3] = Qs[arow + 8 * FQ_STR + kb + 4];
            #pragma unroll
            for (int nt = 0; nt < 16; nt++) {
                const int row = (nt * 8 + fr) * FQ_STR;
                uint32_t bq_[2];
                bq_[0] = Ks[row + kb];
                bq_[1] = Ks[row + kb + 4];
                mma16(s[nt], a, bq_);
            }
        }

        // ---- mask multiply + row max (intra-quad) ----
        const float* mr0 = &mbase[(size_t)(q0 + warp * 16 + fr) * SEQ + t * 128];
        const float* mr1 = mr0 + (size_t)8 * SEQ;
        float m0 = -1e30f, m1 = -1e30f;
        #pragma unroll
        for (int nt = 0; nt < 16; nt++) {
            const int cg = nt * 8 + 2 * fc;
            const float2 k0 = *(const float2*)&mr0[cg];
            const float2 k1 = *(const float2*)&mr1[cg];
            s[nt][0] *= k0.x; s[nt][1] *= k0.y;
            s[nt][2] *= k1.x; s[nt][3] *= k1.y;
            m0 = fmaxf(m0, fmaxf(s[nt][0], s[nt][1]));
            m1 = fmaxf(m1, fmaxf(s[nt][2], s[nt][3]));
        }
        m0 = fmaxf(m0, __shfl_xor_sync(0xffffffffu, m0, 1));
        m0 = fmaxf(m0, __shfl_xor_sync(0xffffffffu, m0, 2));
        m1 = fmaxf(m1, __shfl_xor_sync(0xffffffffu, m1, 1));
        m1 = fmaxf(m1, __shfl_xor_sync(0xffffffffu, m1, 2));

        const float mn0 = fmaxf(rm0, m0);
        const float mn1 = fmaxf(rm1, m1);
        const float al0 = fast_exp2(rm0 - mn0);
        const float al1 = fast_exp2(rm1 - mn1);
        rm0 = mn0; rm1 = mn1;

        #pragma unroll
        for (int nt = 0; nt < 8; nt++) {
            acc_o[nt][0] *= al0; acc_o[nt][1] *= al0;
            acc_o[nt][2] *= al1; acc_o[nt][3] *= al1;
        }

        // ---- p = exp2(s - m), stage P (warp-private rows), row sums ----
        float s0 = 0.0f, s1 = 0.0f;
        #pragma unroll
        for (int nt = 0; nt < 16; nt++) {
            const float p0 = fast_exp2(s[nt][0] - mn0);
            const float p1 = fast_exp2(s[nt][1] - mn0);
            const float p2 = fast_exp2(s[nt][2] - mn1);
            const float p3 = fast_exp2(s[nt][3] - mn1);
            s0 += p0 + p1; s1 += p2 + p3;
            Ps[prow0 + nt * 4 + fc] = bf2(p0, p1);
            Ps[prow1 + nt * 4 + fc] = bf2(p2, p3);
        }
        s0 += __shfl_xor_sync(0xffffffffu, s0, 1);
        s0 += __shfl_xor_sync(0xffffffffu, s0, 2);
        s1 += __shfl_xor_sync(0xffffffffu, s1, 1);
        s1 += __shfl_xor_sync(0xffffffffu, s1, 2);
        rl0 = rl0 * al0 + s0;
        rl1 = rl1 * al1 + s1;

        __syncwarp();   // Ps visible to warp

        // ---- PV: acc_o += P @ V (Vt layout: 1 u32 LDS per b reg) ----
        #pragma unroll
        for (int ks = 0; ks < 8; ks++) {
            uint32_t a[4];
            const int base = prow0 + ks * 8 + fc;
            a[0] = Ps[base];
            a[1] = Ps[base + 8 * FP_STR];
            a[2] = Ps[base + 4];
            a[3] = Ps[base + 8 * FP_STR + 4];
            #pragma unroll
            for (int nt = 0; nt < 8; nt++) {
                const int row = (nt * 8 + fr) * VT_STR;
                uint32_t bv_[2];
                bv_[0] = Vt[row + ks * 8 + fc];
                bv_[1] = Vt[row + ks * 8 + fc + 4];
                mma16(acc_o[nt], a, bv_);
            }
        }
    }

    // ---- normalize and write (bf16) ----
    {
        const int r0 = warp * 16 + fr;
        const float i0 = 1.0f / rl0;
        const float i1 = 1.0f / rl1;
        #pragma unroll
        for (int nt = 0; nt < 8; nt++) {
            const int c = nt * 8 + 2 * fc;
            *(uint32_t*)&Aout[(tb + q0 + r0) * HIDN + h * 64 + c] =
                bf2(acc_o[nt][0] * i0, acc_o[nt][1] * i0);
            *(uint32_t*)&Aout[(tb + q0 + r0 + 8) * HIDN + h * 64 + c] =
                bf2(acc_o[nt][2] * i1, acc_o[nt][3] * i1);
        }
    }
}

// ---------------------------------------------------------------------------
// launch
// ---------------------------------------------------------------------------
extern "C" void kernel_launch(void* const* d_in, const int* in_sizes, int n_in,
                              void* d_out, int out_size)
{
    (void)in_sizes; (void)n_in; (void)out_size;
    const float* x    = (const float*)d_in[0];
    const float* mask = (const float*)d_in[1];
    const float* Wq   = (const float*)d_in[2];
    const float* bq   = (const float*)d_in[3];
    const float* Wk   = (const float*)d_in[4];
    const float* bk   = (const float*)d_in[5];
    const float* Wv   = (const float*)d_in[6];
    const float* bv   = (const float*)d_in[7];
    const float* Wo   = (const float*)d_in[8];
    const float* bo   = (const float*)d_in[9];
    float* out = (float*)d_out;

    __nv_bfloat16 *xb, *WqT, *WkT, *WvT, *WoT, *Qb, *Kb, *Vb, *Ab;
    cudaGetSymbolAddress((void**)&xb,  g_xb);
    cudaGetSymbolAddress((void**)&WqT, g_WqT);
    cudaGetSymbolAddress((void**)&WkT, g_WkT);
    cudaGetSymbolAddress((void**)&WvT, g_WvT);
    cudaGetSymbolAddress((void**)&WoT, g_WoT);
    cudaGetSymbolAddress((void**)&Qb,  g_Qb);
    cudaGetSymbolAddress((void**)&Kb,  g_Kb);
    cudaGetSymbolAddress((void**)&Vb,  g_Vb);
    cudaGetSymbolAddress((void**)&Ab,  g_Ab);

    cudaFuncSetAttribute(fa_kernel, cudaFuncAttributeMaxDynamicSharedMemorySize, FA_SMEM);
    cudaFuncSetAttribute(qkv_gemm_kernel, cudaFuncAttributeMaxDynamicSharedMemorySize, G_SMEM);
    cudaFuncSetAttribute(o_gemm_kernel, cudaFuncAttributeMaxDynamicSharedMemorySize, G_SMEM);

    // prep: bf16 conversions + weight transposes
    cvt_x_kernel<<<2048, 256>>>(x, xb);
    transpose_w_kernel<<<dim3(32, 32), 256>>>(Wq, WqT, HIDN, HIDN);
    transpose_w_kernel<<<dim3(8, 32), 256>>>(Wk, WkT, HIDN, KVN);
    transpose_w_kernel<<<dim3(8, 32), 256>>>(Wv, WvT, HIDN, KVN);
    transpose_w_kernel<<<dim3(32, 32), 256>>>(Wo, WoT, HIDN, HIDN);

    // fused Q/K/V projections (bf16 NT)
    qkv_gemm_kernel<<<dim3(24, 16), 256, G_SMEM>>>(xb, WqT, bq, Qb,
                                                   WkT, bk, Kb, WvT, bv, Vb);
    // fused attention v2
    fa_kernel<<<dim3(8, 64), 256, FA_SMEM>>>(Qb, Kb, Vb, mask, Ab);
    // output projection + bias + residual
    o_gemm_kernel<<<dim3(16, 16), 256, G_SMEM>>>(Ab, WoT, bo, out, x);
}

// round 15
// speedup vs baseline: 1.0318x; 1.0318x over previous
#include <cuda_runtime.h>
#include <cuda_bf16.h>
#include <math.h>
#include <stdint.h>

// Problem constants
#define BATCH 2
#define SEQ   1024
#define TKN   2048      // BATCH*SEQ
#define HIDN  2048
#define NHEADS 32
#define KVN   512       // G*HD = 8*64
#define HD    64

// Scratch (static device arrays: no allocation allowed)
__device__ __nv_bfloat16 g_xb [TKN * HIDN];
__device__ __nv_bfloat16 g_WqT[HIDN * HIDN];
__device__ __nv_bfloat16 g_WkT[KVN * HIDN];
__device__ __nv_bfloat16 g_WvT[KVN * HIDN];
__device__ __nv_bfloat16 g_WoT[HIDN * HIDN];
__device__ __nv_bfloat16 g_Qb [TKN * HIDN];
__device__ __nv_bfloat16 g_Kb [TKN * KVN];
__device__ __nv_bfloat16 g_Vb [TKN * KVN];
__device__ __nv_bfloat16 g_Ab [TKN * HIDN];

// ---------------------------------------------------------------------------
// helpers
// ---------------------------------------------------------------------------
__device__ __forceinline__ uint32_t bf2(float lo, float hi) {
    uint32_t r;
    asm("cvt.rn.bf16x2.f32 %0, %1, %2;" : "=r"(r) : "f"(hi), "f"(lo));
    return r;
}
__device__ __forceinline__ float2 ubf2(uint32_t w) {
    __nv_bfloat162 h = *reinterpret_cast<__nv_bfloat162*>(&w);
    return __bfloat1622float2(h);
}
__device__ __forceinline__ uint32_t s2u(const void* p) {
    return (uint32_t)__cvta_generic_to_shared(p);
}

// mma.sync m16n8k16 bf16: D = A*B + D (fp32 accum)
__device__ __forceinline__ void mma16(float d[4], const uint32_t* a, const uint32_t* b) {
    asm volatile(
        "mma.sync.aligned.m16n8k16.row.col.f32.bf16.bf16.f32 "
        "{%0,%1,%2,%3}, {%4,%5,%6,%7}, {%8,%9}, {%0,%1,%2,%3};\n"
        : "+f"(d[0]), "+f"(d[1]), "+f"(d[2]), "+f"(d[3])
        : "r"(a[0]), "r"(a[1]), "r"(a[2]), "r"(a[3]), "r"(b[0]), "r"(b[1]));
}

// hardware exp2 (MUFU.EX2) — runs on the MUFU pipe, frees FMA slots
__device__ __forceinline__ float ex2f(float x) {
    float r;
    asm("ex2.approx.ftz.f32 %0, %1;" : "=f"(r) : "f"(x));
    return r;
}

__device__ __forceinline__ void cpa16(uint32_t dst, const void* src) {
    asm volatile("cp.async.cg.shared.global [%0], [%1], 16;\n" :: "r"(dst), "l"(src));
}

// ---------------------------------------------------------------------------
// Prep kernels: x fp32 -> bf16; W[K,N] fp32 -> WT[N,K] bf16
// ---------------------------------------------------------------------------
__global__ __launch_bounds__(256) void cvt_x_kernel(const float* __restrict__ x,
                                                    __nv_bfloat16* __restrict__ xb)
{
    const size_t i = ((size_t)blockIdx.x * 256 + threadIdx.x) * 8;
    float4 a = *(const float4*)&x[i];
    float4 b = *(const float4*)&x[i + 4];
    uint4 o;
    o.x = bf2(a.x, a.y); o.y = bf2(a.z, a.w);
    o.z = bf2(b.x, b.y); o.w = bf2(b.z, b.w);
    *(uint4*)&xb[i] = o;
}

__global__ __launch_bounds__(256) void transpose_w_kernel(
    const float* __restrict__ W, __nv_bfloat16* __restrict__ WT, int K, int N)
{
    __shared__ unsigned short t[64][66];
    const int n0 = blockIdx.x * 64, k0 = blockIdx.y * 64;
    const int r = threadIdx.x >> 4, c4 = (threadIdx.x & 15) * 4;
    #pragma unroll
    for (int j = 0; j < 4; j++) {
        const int kk = r + j * 16;
        float4 v = *(const float4*)&W[(size_t)(k0 + kk) * N + n0 + c4];
        uint32_t p0 = bf2(v.x, v.y), p1 = bf2(v.z, v.w);
        t[kk][c4]     = (unsigned short)(p0 & 0xFFFF);
        t[kk][c4 + 1] = (unsigned short)(p0 >> 16);
        t[kk][c4 + 2] = (unsigned short)(p1 & 0xFFFF);
        t[kk][c4 + 3] = (unsigned short)(p1 >> 16);
    }
    __syncthreads();
    #pragma unroll
    for (int j = 0; j < 4; j++) {
        const int nn = r + j * 16;
        uint32_t u0 = (uint32_t)t[c4][nn]     | ((uint32_t)t[c4 + 1][nn] << 16);
        uint32_t u1 = (uint32_t)t[c4 + 2][nn] | ((uint32_t)t[c4 + 3][nn] << 16);
        *(uint2*)&WT[(size_t)(n0 + nn) * K + k0 + c4] = make_uint2(u0, u1);
    }
}

// ---------------------------------------------------------------------------
// NT bf16 GEMM core (R13 proven): C[128,128] = A @ WT^T (+bias, +resid).
// ---------------------------------------------------------------------------
#define GSTR 36               // u32 row stride (32 data + 4 pad) = 144 B
#define GBUF (128 * GSTR)     // u32 per operand buffer (18432 B)
#define G_SMEM (4 * GBUF * 4) // 73728 B

template <bool OUT_BF16>
__device__ __forceinline__ void gemm_nt_core(
    const __nv_bfloat16* __restrict__ Ag, const __nv_bfloat16* __restrict__ Bt,
    const float* __restrict__ bias, void* __restrict__ Cout,
    const float* __restrict__ resid, int Ncols, int mb, int nb)
{
    extern __shared__ __align__(16) uint32_t sh[];
    uint32_t* As = sh;               // [2][GBUF]
    uint32_t* Bs = sh + 2 * GBUF;    // [2][GBUF]

    const int tid = threadIdx.x, lane = tid & 31, warp = tid >> 5;
    const int wm = warp >> 2, wn = warp & 3;
    const int fr = lane >> 2, fc = lane & 3;

    const int lrow = tid >> 1, lhalf = (tid & 1) * 64;
    const uint32_t aDst = s2u(As) + lrow * 144 + lhalf;
    const uint32_t bDst = s2u(Bs) + lrow * 144 + lhalf;
    const __nv_bfloat16* aSrc = Ag + (size_t)(mb + lrow) * HIDN + lhalf / 2;
    const __nv_bfloat16* bSrc = Bt + (size_t)(nb + lrow) * HIDN + lhalf / 2;

    float acc[4][4][4];
    #pragma unroll
    for (int i = 0; i < 4; i++)
        #pragma unroll
        for (int j = 0; j < 4; j++)
            #pragma unroll
            for (int q = 0; q < 4; q++) acc[i][j][q] = 0.0f;

    {
        #pragma unroll
        for (int l = 0; l < 4; l++) {
            cpa16(aDst + l * 16, aSrc + l * 8);
            cpa16(bDst + l * 16, bSrc + l * 8);
        }
        asm volatile("cp.async.commit_group;\n");
    }

    const int nCh = HIDN / 64;   // 32
    for (int it = 0; it < nCh; it++) {
        if (it + 1 < nCh) {
            const int buf = (it + 1) & 1;
            const uint32_t aB = aDst + buf * (GBUF * 4);
            const uint32_t bB = bDst + buf * (GBUF * 4);
            const __nv_bfloat16* as = aSrc + (it + 1) * 64;
            const __nv_bfloat16* bs = bSrc + (it + 1) * 64;
            #pragma unroll
            for (int l = 0; l < 4; l++) {
                cpa16(aB + l * 16, as + l * 8);
                cpa16(bB + l * 16, bs + l * 8);
            }
            asm volatile("cp.async.commit_group;\n");
            asm volatile("cp.async.wait_group 1;\n");
        } else {
            asm volatile("cp.async.wait_group 0;\n");
        }
        __syncthreads();

        const int base = (it & 1) * GBUF;
        #pragma unroll
        for (int ks = 0; ks < 4; ks++) {
            const int kb = ks * 8 + fc;
            uint32_t a[4][4], b[4][2];
            #pragma unroll
            for (int mt = 0; mt < 4; mt++) {
                const int row = base + (wm * 64 + mt * 16 + fr) * GSTR;
                a[mt][0] = As[row + kb];
                a[mt][1] = As[row + 8 * GSTR + kb];
                a[mt][2] = As[row + kb + 4];
                a[mt][3] = As[row + 8 * GSTR + kb + 4];
            }
            #pragma unroll
            for (int nt = 0; nt < 4; nt++) {
                const int row = base + (wn * 32 + nt * 8 + fr) * GSTR;
                b[nt][0] = Bs[row + kb];
                b[nt][1] = Bs[row + kb + 4];
            }
            #pragma unroll
            for (int mt = 0; mt < 4; mt++)
                #pragma unroll
                for (int nt = 0; nt < 4; nt++)
                    mma16(acc[mt][nt], a[mt], b[nt]);
        }
        __syncthreads();
    }

    const int r0 = mb + wm * 64 + fr;
    const int c0 = nb + wn * 32 + fc * 2;
    #pragma unroll
    for (int mt = 0; mt < 4; mt++) {
        #pragma unroll
        for (int nt = 0; nt < 4; nt++) {
            const int r = r0 + mt * 16;
            const int c = c0 + nt * 8;
            const float bx = bias[c], by = bias[c + 1];
            if (OUT_BF16) {
                __nv_bfloat16* C = (__nv_bfloat16*)Cout;
                *(uint32_t*)&C[(size_t)r * Ncols + c] =
                    bf2(acc[mt][nt][0] + bx, acc[mt][nt][1] + by);
                *(uint32_t*)&C[(size_t)(r + 8) * Ncols + c] =
                    bf2(acc[mt][nt][2] + bx, acc[mt][nt][3] + by);
            } else {
                float* C = (float*)Cout;
                const float2 u0 = *(const float2*)&resid[(size_t)r * Ncols + c];
                const float2 u1 = *(const float2*)&resid[(size_t)(r + 8) * Ncols + c];
                *(float2*)&C[(size_t)r * Ncols + c] =
                    make_float2(acc[mt][nt][0] + bx + u0.x, acc[mt][nt][1] + by + u0.y);
                *(float2*)&C[(size_t)(r + 8) * Ncols + c] =
                    make_float2(acc[mt][nt][2] + bx + u1.x, acc[mt][nt][3] + by + u1.y);
            }
        }
    }
}

// Fused Q/K/V projection: blockIdx.x [0,16)->Q, [16,20)->K, [20,24)->V.
__global__ __launch_bounds__(256, 2) void qkv_gemm_kernel(
    const __nv_bfloat16* __restrict__ xb,
    const __nv_bfloat16* __restrict__ WqT, const float* __restrict__ bq, __nv_bfloat16* __restrict__ Qb,
    const __nv_bfloat16* __restrict__ WkT, const float* __restrict__ bk, __nv_bfloat16* __restrict__ Kb,
    const __nv_bfloat16* __restrict__ WvT, const float* __restrict__ bv, __nv_bfloat16* __restrict__ Vb)
{
    const int bx = blockIdx.x, mrow = blockIdx.y * 128;
    if (bx < 16)
        gemm_nt_core<true>(xb, WqT, bq, Qb, nullptr, HIDN, mrow, bx * 128);
    else if (bx < 20)
        gemm_nt_core<true>(xb, WkT, bk, Kb, nullptr, KVN, mrow, (bx - 16) * 128);
    else
        gemm_nt_core<true>(xb, WvT, bv, Vb, nullptr, KVN, mrow, (bx - 20) * 128);
}

// O projection: fp32 out + bias + residual.
__global__ __launch_bounds__(256, 2) void o_gemm_kernel(
    const __nv_bfloat16* __restrict__ Ab, const __nv_bfloat16* __restrict__ WoT,
    const float* __restrict__ bo, float* __restrict__ out,
    const float* __restrict__ resid)
{
    gemm_nt_core<false>(Ab, WoT, bo, out, resid, HIDN,
                        blockIdx.y * 128, blockIdx.x * 128);
}

// ---------------------------------------------------------------------------
// Fused flash attention v2 (R14) + MUFU.EX2 softmax.
// block = (b,h,128 q rows); warp owns 16 rows x all 128 keys.
// Online-softmax state in registers; 2 syncthreads + 1 syncwarp per tile.
// ---------------------------------------------------------------------------
#define FQ_STR 36   // Qs/Ks u32 row stride
#define FP_STR 68   // Ps  u32 row stride
#define VT_STR 68   // Vt  u32 row stride (keypairs)

#define FA_QS   0
#define FA_KS   (128 * FQ_STR)               // 4608
#define FA_VT   (2 * 128 * FQ_STR)           // 9216
#define FA_PS   (FA_VT + 64 * VT_STR)        // 13568
#define FA_U32S (FA_PS + 128 * FP_STR)       // 22272
#define FA_SMEM (FA_U32S * 4)                // 89088 B

__global__ __launch_bounds__(256, 2) void fa_kernel(
    const __nv_bfloat16* __restrict__ Q, const __nv_bfloat16* __restrict__ K,
    const __nv_bfloat16* __restrict__ V, const float* __restrict__ mask,
    __nv_bfloat16* __restrict__ Aout)
{
    extern __shared__ uint32_t shu[];
    uint32_t* Qs = shu + FA_QS;
    uint32_t* Ks = shu + FA_KS;
    uint32_t* Vt = shu + FA_VT;
    uint32_t* Ps = shu + FA_PS;
    unsigned short* Vt16 = (unsigned short*)Vt;

    const int tid = threadIdx.x, lane = tid & 31, warp = tid >> 5;
    const int z = blockIdx.y, b = z >> 5, h = z & 31, g = h >> 2;
    const int q0 = blockIdx.x * 128;
    const size_t tb = (size_t)b * SEQ;
    const float* mbase = mask + (size_t)b * SEQ * SEQ;

    const int fr = lane >> 2, fc = lane & 3;

    // load Q tile (bf16), prescale by (1/8)*log2(e)
    const float qsc = 0.125f * 1.4426950408889634f;
    {
        const int r = tid >> 4, c = (tid & 15) * 4;
        const uint32_t* qp = (const uint32_t*)Q;
        #pragma unroll
        for (int p = 0; p < 8; p++) {
            const int row = r + p * 16;
            const size_t w = ((tb + q0 + row) * HIDN + h * 64 + c) >> 1;
            float2 f0 = ubf2(qp[w]), f1 = ubf2(qp[w + 1]);
            Qs[row * FQ_STR + (c >> 1)]     = bf2(f0.x * qsc, f0.y * qsc);
            Qs[row * FQ_STR + (c >> 1) + 1] = bf2(f1.x * qsc, f1.y * qsc);
        }
    }

    // register-resident online softmax state (rows warp*16+fr, +8+fr)
    float rm0 = -1e30f, rm1 = -1e30f, rl0 = 0.0f, rl1 = 0.0f;

    float acc_o[8][4];
    #pragma unroll
    for (int i = 0; i < 8; i++)
        #pragma unroll
        for (int q = 0; q < 4; q++) acc_o[i][q] = 0.0f;

    const int arow = (warp * 16 + fr) * FQ_STR;
    const int prow0 = (warp * 16 + fr) * FP_STR;
    const int prow1 = prow0 + 8 * FP_STR;

    for (int t = 0; t < 8; t++) {
        __syncthreads();   // all warps done reading Ks/Vt of prev tile
        {
            const int r = tid >> 4, c = (tid & 15) * 4;
            const uint32_t* kp = (const uint32_t*)K;
            const uint32_t* vp = (const uint32_t*)V;
            #pragma unroll
            for (int p = 0; p < 8; p++) {
                const int row = r + p * 16;
                const size_t w = ((tb + t * 128 + row) * KVN + g * 64 + c) >> 1;
                Ks[row * FQ_STR + (c >> 1)]     = kp[w];
                Ks[row * FQ_STR + (c >> 1) + 1] = kp[w + 1];
                const uint32_t v0 = vp[w], v1 = vp[w + 1];
                Vt16[(c + 0) * (2 * VT_STR) + row] = (unsigned short)(v0 & 0xFFFF);
                Vt16[(c + 1) * (2 * VT_STR) + row] = (unsigned short)(v0 >> 16);
                Vt16[(c + 2) * (2 * VT_STR) + row] = (unsigned short)(v1 & 0xFFFF);
                Vt16[(c + 3) * (2 * VT_STR) + row] = (unsigned short)(v1 >> 16);
            }
        }
        __syncthreads();

        // ---- S = Qs @ Ks^T: warp's 16 rows x 128 keys ----
        float s[16][4];
        #pragma unroll
        for (int i = 0; i < 16; i++)
            #pragma unroll
            for (int q = 0; q < 4; q++) s[i][q] = 0.0f;

        #pragma unroll
        for (int ks = 0; ks < 4; ks++) {
            const int kb = ks * 8 + fc;
            uint32_t a[4];
            a[0] = Qs[arow + kb];
            a[1] = Qs[arow + 8 * FQ_STR + kb];
            a[2] = Qs[arow + kb + 4];
            a[3] = Qs[arow + 8 * FQ_STR + kb + 4];
            #pragma unroll
            for (int nt = 0; nt < 16; nt++) {
                const int row = (nt * 8 + fr) * FQ_STR;
                uint32_t bq_[2];
                bq_[0] = Ks[row + kb];
                bq_[1] = Ks[row + kb + 4];
                mma16(s[nt], a, bq_);
            }
        }

        // ---- mask multiply + row max (intra-quad) ----
        const float* mr0 = &mbase[(size_t)(q0 + warp * 16 + fr) * SEQ + t * 128];
        const float* mr1 = mr0 + (size_t)8 * SEQ;
        float m0 = -1e30f, m1 = -1e30f;
        #pragma unroll
        for (int nt = 0; nt < 16; nt++) {
            const int cg = nt * 8 + 2 * fc;
            const float2 k0 = *(const float2*)&mr0[cg];
            const float2 k1 = *(const float2*)&mr1[cg];
            s[nt][0] *= k0.x; s[nt][1] *= k0.y;
            s[nt][2] *= k1.x; s[nt][3] *= k1.y;
            m0 = fmaxf(m0, fmaxf(s[nt][0], s[nt][1]));
            m1 = fmaxf(m1, fmaxf(s[nt][2], s[nt][3]));
        }
        m0 = fmaxf(m0, __shfl_xor_sync(0xffffffffu, m0, 1));
        m0 = fmaxf(m0, __shfl_xor_sync(0xffffffffu, m0, 2));
        m1 = fmaxf(m1, __shfl_xor_sync(0xffffffffu, m1, 1));
        m1 = fmaxf(m1, __shfl_xor_sync(0xffffffffu, m1, 2));

        const float mn0 = fmaxf(rm0, m0);
        const float mn1 = fmaxf(rm1, m1);
        const float al0 = ex2f(rm0 - mn0);
        const float al1 = ex2f(rm1 - mn1);
        rm0 = mn0; rm1 = mn1;

        #pragma unroll
        for (int nt = 0; nt < 8; nt++) {
            acc_o[nt][0] *= al0; acc_o[nt][1] *= al0;
            acc_o[nt][2] *= al1; acc_o[nt][3] *= al1;
        }

        // ---- p = exp2(s - m) via MUFU, stage P, row sums ----
        float s0 = 0.0f, s1 = 0.0f;
        #pragma unroll
        for (int nt = 0; nt < 16; nt++) {
            const float p0 = ex2f(s[nt][0] - mn0);
            const float p1 = ex2f(s[nt][1] - mn0);
            const float p2 = ex2f(s[nt][2] - mn1);
            const float p3 = ex2f(s[nt][3] - mn1);
            s0 += p0 + p1; s1 += p2 + p3;
            Ps[prow0 + nt * 4 + fc] = bf2(p0, p1);
            Ps[prow1 + nt * 4 + fc] = bf2(p2, p3);
        }
        s0 += __shfl_xor_sync(0xffffffffu, s0, 1);
        s0 += __shfl_xor_sync(0xffffffffu, s0, 2);
        s1 += __shfl_xor_sync(0xffffffffu, s1, 1);
        s1 += __shfl_xor_sync(0xffffffffu, s1, 2);
        rl0 = rl0 * al0 + s0;
        rl1 = rl1 * al1 + s1;

        __syncwarp();   // Ps visible to warp

        // ---- PV: acc_o += P @ V (Vt layout: 1 u32 LDS per b reg) ----
        #pragma unroll
        for (int ks = 0; ks < 8; ks++) {
            uint32_t a[4];
            const int base = prow0 + ks * 8 + fc;
            a[0] = Ps[base];
            a[1] = Ps[base + 8 * FP_STR];
            a[2] = Ps[base + 4];
            a[3] = Ps[base + 8 * FP_STR + 4];
            #pragma unroll
            for (int nt = 0; nt < 8; nt++) {
                const int row = (nt * 8 + fr) * VT_STR;
                uint32_t bv_[2];
                bv_[0] = Vt[row + ks * 8 + fc];
                bv_[1] = Vt[row + ks * 8 + fc + 4];
                mma16(acc_o[nt], a, bv_);
            }
        }
    }

    // ---- normalize and write (bf16) ----
    {
        const int r0 = warp * 16 + fr;
        const float i0 = 1.0f / rl0;
        const float i1 = 1.0f / rl1;
        #pragma unroll
        for (int nt = 0; nt < 8; nt++) {
            const int c = nt * 8 + 2 * fc;
            *(uint32_t*)&Aout[(tb + q0 + r0) * HIDN + h * 64 + c] =
                bf2(acc_o[nt][0] * i0, acc_o[nt][1] * i0);
            *(uint32_t*)&Aout[(tb + q0 + r0 + 8) * HIDN + h * 64 + c] =
                bf2(acc_o[nt][2] * i1, acc_o[nt][3] * i1);
        }
    }
}

// ---------------------------------------------------------------------------
// launch
// ---------------------------------------------------------------------------
extern "C" void kernel_launch(void* const* d_in, const int* in_sizes, int n_in,
                              void* d_out, int out_size)
{
    (void)in_sizes; (void)n_in; (void)out_size;
    const float* x    = (const float*)d_in[0];
    const float* mask = (const float*)d_in[1];
    const float* Wq   = (const float*)d_in[2];
    const float* bq   = (const float*)d_in[3];
    const float* Wk   = (const float*)d_in[4];
    const float* bk   = (const float*)d_in[5];
    const float* Wv   = (const float*)d_in[6];
    const float* bv   = (const float*)d_in[7];
    const float* Wo   = (const float*)d_in[8];
    const float* bo   = (const float*)d_in[9];
    float* out = (float*)d_out;

    __nv_bfloat16 *xb, *WqT, *WkT, *WvT, *WoT, *Qb, *Kb, *Vb, *Ab;
    cudaGetSymbolAddress((void**)&xb,  g_xb);
    cudaGetSymbolAddress((void**)&WqT, g_WqT);
    cudaGetSymbolAddress((void**)&WkT, g_WkT);
    cudaGetSymbolAddress((void**)&WvT, g_WvT);
    cudaGetSymbolAddress((void**)&WoT, g_WoT);
    cudaGetSymbolAddress((void**)&Qb,  g_Qb);
    cudaGetSymbolAddress((void**)&Kb,  g_Kb);
    cudaGetSymbolAddress((void**)&Vb,  g_Vb);
    cudaGetSymbolAddress((void**)&Ab,  g_Ab);

    cudaFuncSetAttribute(fa_kernel, cudaFuncAttributeMaxDynamicSharedMemorySize, FA_SMEM);
    cudaFuncSetAttribute(qkv_gemm_kernel, cudaFuncAttributeMaxDynamicSharedMemorySize, G_SMEM);
    cudaFuncSetAttribute(o_gemm_kernel, cudaFuncAttributeMaxDynamicSharedMemorySize, G_SMEM);

    // prep: bf16 conversions + weight transposes
    cvt_x_kernel<<<2048, 256>>>(x, xb);
    transpose_w_kernel<<<dim3(32, 32), 256>>>(Wq, WqT, HIDN, HIDN);
    transpose_w_kernel<<<dim3(8, 32), 256>>>(Wk, WkT, HIDN, KVN);
    transpose_w_kernel<<<dim3(8, 32), 256>>>(Wv, WvT, HIDN, KVN);
    transpose_w_kernel<<<dim3(32, 32), 256>>>(Wo, WoT, HIDN, HIDN);

    // fused Q/K/V projections (bf16 NT)
    qkv_gemm_kernel<<<dim3(24, 16), 256, G_SMEM>>>(xb, WqT, bq, Qb,
                                                   WkT, bk, Kb, WvT, bv, Vb);
    // fused attention v2 + MUFU softmax
    fa_kernel<<<dim3(8, 64), 256, FA_SMEM>>>(Qb, Kb, Vb, mask, Ab);
    // output projection + bias + residual
    o_gemm_kernel<<<dim3(16, 16), 256, G_SMEM>>>(Ab, WoT, bo, out, x);
}

// round 17
// speedup vs baseline: 1.0586x; 1.0260x over previous
#include <cuda_runtime.h>
#include <cuda_bf16.h>
#include <math.h>
#include <stdint.h>

// Problem constants
#define BATCH 2
#define SEQ   1024
#define TKN   2048      // BATCH*SEQ
#define HIDN  2048
#define NHEADS 32
#define KVN   512       // G*HD = 8*64
#define HD    64

// Scratch (static device arrays: no allocation allowed)
__device__ __nv_bfloat16 g_xb [TKN * HIDN];
__device__ __nv_bfloat16 g_mb [BATCH * SEQ * SEQ];
__device__ __nv_bfloat16 g_WqT[HIDN * HIDN];
__device__ __nv_bfloat16 g_WkT[KVN * HIDN];
__device__ __nv_bfloat16 g_WvT[KVN * HIDN];
__device__ __nv_bfloat16 g_WoT[HIDN * HIDN];
__device__ __nv_bfloat16 g_Qb [TKN * HIDN];
__device__ __nv_bfloat16 g_Kb [TKN * KVN];
__device__ __nv_bfloat16 g_Vb [TKN * KVN];
__device__ __nv_bfloat16 g_Ab [TKN * HIDN];

// ---------------------------------------------------------------------------
// helpers
// ---------------------------------------------------------------------------
__device__ __forceinline__ uint32_t bf2(float lo, float hi) {
    uint32_t r;
    asm("cvt.rn.bf16x2.f32 %0, %1, %2;" : "=r"(r) : "f"(hi), "f"(lo));
    return r;
}
__device__ __forceinline__ float2 ubf2(uint32_t w) {
    __nv_bfloat162 h = *reinterpret_cast<__nv_bfloat162*>(&w);
    return __bfloat1622float2(h);
}
__device__ __forceinline__ uint32_t s2u(const void* p) {
    return (uint32_t)__cvta_generic_to_shared(p);
}

// mma.sync m16n8k16 bf16: D = A*B + D (fp32 accum)
__device__ __forceinline__ void mma16(float d[4], const uint32_t* a, const uint32_t* b) {
    asm volatile(
        "mma.sync.aligned.m16n8k16.row.col.f32.bf16.bf16.f32 "
        "{%0,%1,%2,%3}, {%4,%5,%6,%7}, {%8,%9}, {%0,%1,%2,%3};\n"
        : "+f"(d[0]), "+f"(d[1]), "+f"(d[2]), "+f"(d[3])
        : "r"(a[0]), "r"(a[1]), "r"(a[2]), "r"(a[3]), "r"(b[0]), "r"(b[1]));
}

// hardware exp2 (MUFU.EX2) — runs on the MUFU pipe, frees FMA slots
__device__ __forceinline__ float ex2f(float x) {
    float r;
    asm("ex2.approx.ftz.f32 %0, %1;" : "=f"(r) : "f"(x));
    return r;
}

__device__ __forceinline__ void cpa16(uint32_t dst, const void* src) {
    asm volatile("cp.async.cg.shared.global [%0], [%1], 16;\n" :: "r"(dst), "l"(src));
}

// ---------------------------------------------------------------------------
// Fused prep kernel: one launch does
//   [0, 2048)     : x fp32 -> bf16           (4M elems, 8/thread)
//   [2048, 3072)  : mask fp32 -> bf16        (2M elems, 8/thread)
//   [3072, 4096)  : Wq transpose  (32x32 tiles of 64x64)
//   [4096, 4352)  : Wk transpose  (8x32)
//   [4352, 4608)  : Wv transpose  (8x32)
//   [4608, 5632)  : Wo transpose  (32x32)
// ---------------------------------------------------------------------------
__device__ __forceinline__ void cvt8(const float* __restrict__ src,
                                     __nv_bfloat16* __restrict__ dst,
                                     int blk)
{
    const size_t i = ((size_t)blk * 256 + threadIdx.x) * 8;
    float4 a = *(const float4*)&src[i];
    float4 b = *(const float4*)&src[i + 4];
    uint4 o;
    o.x = bf2(a.x, a.y); o.y = bf2(a.z, a.w);
    o.z = bf2(b.x, b.y); o.w = bf2(b.z, b.w);
    *(uint4*)&dst[i] = o;
}

__device__ __forceinline__ void transpose64(
    const float* __restrict__ W, __nv_bfloat16* __restrict__ WT,
    int K, int N, int n0, int k0, unsigned short (*t)[66])
{
    const int r = threadIdx.x >> 4, c4 = (threadIdx.x & 15) * 4;
    #pragma unroll
    for (int j = 0; j < 4; j++) {
        const int kk = r + j * 16;
        float4 v = *(const float4*)&W[(size_t)(k0 + kk) * N + n0 + c4];
        uint32_t p0 = bf2(v.x, v.y), p1 = bf2(v.z, v.w);
        t[kk][c4]     = (unsigned short)(p0 & 0xFFFF);
        t[kk][c4 + 1] = (unsigned short)(p0 >> 16);
        t[kk][c4 + 2] = (unsigned short)(p1 & 0xFFFF);
        t[kk][c4 + 3] = (unsigned short)(p1 >> 16);
    }
    __syncthreads();
    #pragma unroll
    for (int j = 0; j < 4; j++) {
        const int nn = r + j * 16;
        uint32_t u0 = (uint32_t)t[c4][nn]     | ((uint32_t)t[c4 + 1][nn] << 16);
        uint32_t u1 = (uint32_t)t[c4 + 2][nn] | ((uint32_t)t[c4 + 3][nn] << 16);
        *(uint2*)&WT[(size_t)(n0 + nn) * K + k0 + c4] = make_uint2(u0, u1);
    }
}

__global__ __launch_bounds__(256) void prep_kernel(
    const float* __restrict__ x,   __nv_bfloat16* __restrict__ xb,
    const float* __restrict__ msk, __nv_bfloat16* __restrict__ mb,
    const float* __restrict__ Wq,  __nv_bfloat16* __restrict__ WqT,
    const float* __restrict__ Wk,  __nv_bfloat16* __restrict__ WkT,
    const float* __restrict__ Wv,  __nv_bfloat16* __restrict__ WvT,
    const float* __restrict__ Wo,  __nv_bfloat16* __restrict__ WoT)
{
    __shared__ unsigned short t[64][66];
    const int bx = blockIdx.x;
    if (bx < 2048) {
        cvt8(x, xb, bx);
    } else if (bx < 3072) {
        cvt8(msk, mb, bx - 2048);
    } else if (bx < 4096) {
        const int i = bx - 3072;
        transpose64(Wq, WqT, HIDN, HIDN, (i & 31) * 64, (i >> 5) * 64, t);
    } else if (bx < 4352) {
        const int i = bx - 4096;
        transpose64(Wk, WkT, HIDN, KVN, (i & 7) * 64, (i >> 3) * 64, t);
    } else if (bx < 4608) {
        const int i = bx - 4352;
        transpose64(Wv, WvT, HIDN, KVN, (i & 7) * 64, (i >> 3) * 64, t);
    } else {
        const int i = bx - 4608;
        transpose64(Wo, WoT, HIDN, HIDN, (i & 31) * 64, (i >> 5) * 64, t);
    }
}

// ---------------------------------------------------------------------------
// NT bf16 GEMM core (R13 proven): C[128,128] = A @ WT^T (+bias, +resid).
// ---------------------------------------------------------------------------
#define GSTR 36               // u32 row stride (32 data + 4 pad) = 144 B
#define GBUF (128 * GSTR)     // u32 per operand buffer (18432 B)
#define G_SMEM (4 * GBUF * 4) // 73728 B

template <bool OUT_BF16>
__device__ __forceinline__ void gemm_nt_core(
    const __nv_bfloat16* __restrict__ Ag, const __nv_bfloat16* __restrict__ Bt,
    const float* __restrict__ bias, void* __restrict__ Cout,
    const float* __restrict__ resid, int Ncols, int mb, int nb)
{
    extern __shared__ __align__(16) uint32_t sh[];
    uint32_t* As = sh;               // [2][GBUF]
    uint32_t* Bs = sh + 2 * GBUF;    // [2][GBUF]

    const int tid = threadIdx.x, lane = tid & 31, warp = tid >> 5;
    const int wm = warp >> 2, wn = warp & 3;
    const int fr = lane >> 2, fc = lane & 3;

    const int lrow = tid >> 1, lhalf = (tid & 1) * 64;
    const uint32_t aDst = s2u(As) + lrow * 144 + lhalf;
    const uint32_t bDst = s2u(Bs) + lrow * 144 + lhalf;
    const __nv_bfloat16* aSrc = Ag + (size_t)(mb + lrow) * HIDN + lhalf / 2;
    const __nv_bfloat16* bSrc = Bt + (size_t)(nb + lrow) * HIDN + lhalf / 2;

    float acc[4][4][4];
    #pragma unroll
    for (int i = 0; i < 4; i++)
        #pragma unroll
        for (int j = 0; j < 4; j++)
            #pragma unroll
            for (int q = 0; q < 4; q++) acc[i][j][q] = 0.0f;

    {
        #pragma unroll
        for (int l = 0; l < 4; l++) {
            cpa16(aDst + l * 16, aSrc + l * 8);
            cpa16(bDst + l * 16, bSrc + l * 8);
        }
        asm volatile("cp.async.commit_group;\n");
    }

    const int nCh = HIDN / 64;   // 32
    for (int it = 0; it < nCh; it++) {
        if (it + 1 < nCh) {
            const int buf = (it + 1) & 1;
            const uint32_t aB = aDst + buf * (GBUF * 4);
            const uint32_t bB = bDst + buf * (GBUF * 4);
            const __nv_bfloat16* as = aSrc + (it + 1) * 64;
            const __nv_bfloat16* bs = bSrc + (it + 1) * 64;
            #pragma unroll
            for (int l = 0; l < 4; l++) {
                cpa16(aB + l * 16, as + l * 8);
                cpa16(bB + l * 16, bs + l * 8);
            }
            asm volatile("cp.async.commit_group;\n");
            asm volatile("cp.async.wait_group 1;\n");
        } else {
            asm volatile("cp.async.wait_group 0;\n");
        }
        __syncthreads();

        const int base = (it & 1) * GBUF;
        #pragma unroll
        for (int ks = 0; ks < 4; ks++) {
            const int kb = ks * 8 + fc;
            uint32_t a[4][4], b[4][2];
            #pragma unroll
            for (int mt = 0; mt < 4; mt++) {
                const int row = base + (wm * 64 + mt * 16 + fr) * GSTR;
                a[mt][0] = As[row + kb];
                a[mt][1] = As[row + 8 * GSTR + kb];
                a[mt][2] = As[row + kb + 4];
                a[mt][3] = As[row + 8 * GSTR + kb + 4];
            }
            #pragma unroll
            for (int nt = 0; nt < 4; nt++) {
                const int row = base + (wn * 32 + nt * 8 + fr) * GSTR;
                b[nt][0] = Bs[row + kb];
                b[nt][1] = Bs[row + kb + 4];
            }
            #pragma unroll
            for (int mt = 0; mt < 4; mt++)
                #pragma unroll
                for (int nt = 0; nt < 4; nt++)
                    mma16(acc[mt][nt], a[mt], b[nt]);
        }
        __syncthreads();
    }

    const int r0 = mb + wm * 64 + fr;
    const int c0 = nb + wn * 32 + fc * 2;
    #pragma unroll
    for (int mt = 0; mt < 4; mt++) {
        #pragma unroll
        for (int nt = 0; nt < 4; nt++) {
            const int r = r0 + mt * 16;
            const int c = c0 + nt * 8;
            const float bx = bias[c], by = bias[c + 1];
            if (OUT_BF16) {
                __nv_bfloat16* C = (__nv_bfloat16*)Cout;
                *(uint32_t*)&C[(size_t)r * Ncols + c] =
                    bf2(acc[mt][nt][0] + bx, acc[mt][nt][1] + by);
                *(uint32_t*)&C[(size_t)(r + 8) * Ncols + c] =
                    bf2(acc[mt][nt][2] + bx, acc[mt][nt][3] + by);
            } else {
                float* C = (float*)Cout;
                const float2 u0 = *(const float2*)&resid[(size_t)r * Ncols + c];
                const float2 u1 = *(const float2*)&resid[(size_t)(r + 8) * Ncols + c];
                *(float2*)&C[(size_t)r * Ncols + c] =
                    make_float2(acc[mt][nt][0] + bx + u0.x, acc[mt][nt][1] + by + u0.y);
                *(float2*)&C[(size_t)(r + 8) * Ncols + c] =
                    make_float2(acc[mt][nt][2] + bx + u1.x, acc[mt][nt][3] + by + u1.y);
            }
        }
    }
}

// Fused Q/K/V projection: blockIdx.x [0,16)->Q, [16,20)->K, [20,24)->V.
__global__ __launch_bounds__(256, 2) void qkv_gemm_kernel(
    const __nv_bfloat16* __restrict__ xb,
    const __nv_bfloat16* __restrict__ WqT, const float* __restrict__ bq, __nv_bfloat16* __restrict__ Qb,
    const __nv_bfloat16* __restrict__ WkT, const float* __restrict__ bk, __nv_bfloat16* __restrict__ Kb,
    const __nv_bfloat16* __restrict__ WvT, const float* __restrict__ bv, __nv_bfloat16* __restrict__ Vb)
{
    const int bx = blockIdx.x, mrow = blockIdx.y * 128;
    if (bx < 16)
        gemm_nt_core<true>(xb, WqT, bq, Qb, nullptr, HIDN, mrow, bx * 128);
    else if (bx < 20)
        gemm_nt_core<true>(xb, WkT, bk, Kb, nullptr, KVN, mrow, (bx - 16) * 128);
    else
        gemm_nt_core<true>(xb, WvT, bv, Vb, nullptr, KVN, mrow, (bx - 20) * 128);
}

// O projection: fp32 out + bias + residual.
__global__ __launch_bounds__(256, 2) void o_gemm_kernel(
    const __nv_bfloat16* __restrict__ Ab, const __nv_bfloat16* __restrict__ WoT,
    const float* __restrict__ bo, float* __restrict__ out,
    const float* __restrict__ resid)
{
    gemm_nt_core<false>(Ab, WoT, bo, out, resid, HIDN,
                        blockIdx.y * 128, blockIdx.x * 128);
}

// ---------------------------------------------------------------------------
// Fused flash attention v2 + MUFU.EX2 softmax + bf16 mask.
// block = (b,h,128 q rows); warp owns 16 rows x all 128 keys.
// Online-softmax state in registers; 2 syncthreads + 1 syncwarp per tile.
// ---------------------------------------------------------------------------
#define FQ_STR 36   // Qs/Ks u32 row stride
#define FP_STR 68   // Ps  u32 row stride
#define VT_STR 68   // Vt  u32 row stride (keypairs)

#define FA_QS   0
#define FA_KS   (128 * FQ_STR)               // 4608
#define FA_VT   (2 * 128 * FQ_STR)           // 9216
#define FA_PS   (FA_VT + 64 * VT_STR)        // 13568
#define FA_U32S (FA_PS + 128 * FP_STR)       // 22272
#define FA_SMEM (FA_U32S * 4)                // 89088 B

__global__ __launch_bounds__(256, 2) void fa_kernel(
    const __nv_bfloat16* __restrict__ Q, const __nv_bfloat16* __restrict__ K,
    const __nv_bfloat16* __restrict__ V, const __nv_bfloat16* __restrict__ maskb,
    __nv_bfloat16* __restrict__ Aout)
{
    extern __shared__ uint32_t shu[];
    uint32_t* Qs = shu + FA_QS;
    uint32_t* Ks = shu + FA_KS;
    uint32_t* Vt = shu + FA_VT;
    uint32_t* Ps = shu + FA_PS;
    unsigned short* Vt16 = (unsigned short*)Vt;

    const int tid = threadIdx.x, lane = tid & 31, warp = tid >> 5;
    const int z = blockIdx.y, b = z >> 5, h = z & 31, g = h >> 2;
    const int q0 = blockIdx.x * 128;
    const size_t tb = (size_t)b * SEQ;
    // bf16 mask, viewed as u32 pairs (row stride SEQ/2 u32)
    const uint32_t* mbase = (const uint32_t*)(maskb + (size_t)b * SEQ * SEQ);

    const int fr = lane >> 2, fc = lane & 3;

    // load Q tile (bf16), prescale by (1/8)*log2(e)
    const float qsc = 0.125f * 1.4426950408889634f;
    {
        const int r = tid >> 4, c = (tid & 15) * 4;
        const uint32_t* qp = (const uint32_t*)Q;
        #pragma unroll
        for (int p = 0; p < 8; p++) {
            const int row = r + p * 16;
            const size_t w = ((tb + q0 + row) * HIDN + h * 64 + c) >> 1;
            float2 f0 = ubf2(qp[w]), f1 = ubf2(qp[w + 1]);
            Qs[row * FQ_STR + (c >> 1)]     = bf2(f0.x * qsc, f0.y * qsc);
            Qs[row * FQ_STR + (c >> 1) + 1] = bf2(f1.x * qsc, f1.y * qsc);
        }
    }

    // register-resident online softmax state (rows warp*16+fr, +8+fr)
    float rm0 = -1e30f, rm1 = -1e30f, rl0 = 0.0f, rl1 = 0.0f;

    float acc_o[8][4];
    #pragma unroll
    for (int i = 0; i < 8; i++)
        #pragma unroll
        for (int q = 0; q < 4; q++) acc_o[i][q] = 0.0f;

    const int arow = (warp * 16 + fr) * FQ_STR;
    const int prow0 = (warp * 16 + fr) * FP_STR;
    const int prow1 = prow0 + 8 * FP_STR;

    for (int t = 0; t < 8; t++) {
        __syncthreads();   // all warps done reading Ks/Vt of prev tile
        {
            const int r = tid >> 4, c = (tid & 15) * 4;
            const uint32_t* kp = (const uint32_t*)K;
            const uint32_t* vp = (const uint32_t*)V;
            #pragma unroll
            for (int p = 0; p < 8; p++) {
                const int row = r + p * 16;
                const size_t w = ((tb + t * 128 + row) * KVN + g * 64 + c) >> 1;
                Ks[row * FQ_STR + (c >> 1)]     = kp[w];
                Ks[row * FQ_STR + (c >> 1) + 1] = kp[w + 1];
                const uint32_t v0 = vp[w], v1 = vp[w + 1];
                Vt16[(c + 0) * (2 * VT_STR) + row] = (unsigned short)(v0 & 0xFFFF);
                Vt16[(c + 1) * (2 * VT_STR) + row] = (unsigned short)(v0 >> 16);
                Vt16[(c + 2) * (2 * VT_STR) + row] = (unsigned short)(v1 & 0xFFFF);
                Vt16[(c + 3) * (2 * VT_STR) + row] = (unsigned short)(v1 >> 16);
            }
        }
        __syncthreads();

        // ---- S = Qs @ Ks^T: warp's 16 rows x 128 keys ----
        float s[16][4];
        #pragma unroll
        for (int i = 0; i < 16; i++)
            #pragma unroll
            for (int q = 0; q < 4; q++) s[i][q] = 0.0f;

        #pragma unroll
        for (int ks = 0; ks < 4; ks++) {
            const int kb = ks * 8 + fc;
            uint32_t a[4];
            a[0] = Qs[arow + kb];
            a[1] = Qs[arow + 8 * FQ_STR + kb];
            a[2] = Qs[arow + kb + 4];
            a[3] = Qs[arow + 8 * FQ_STR + kb + 4];
            #pragma unroll
            for (int nt = 0; nt < 16; nt++) {
                const int row = (nt * 8 + fr) * FQ_STR;
                uint32_t bq_[2];
                bq_[0] = Ks[row + kb];
                bq_[1] = Ks[row + kb + 4];
                mma16(s[nt], a, bq_);
            }
        }

        // ---- mask multiply (bf16 mask, u32 per 2 cols) + row max ----
        const uint32_t* mr0 = mbase +
            (((size_t)(q0 + warp * 16 + fr) * SEQ + t * 128) >> 1);
        const uint32_t* mr1 = mr0 + 4 * SEQ;   // +8 rows (SEQ/2 u32 each)
        float m0 = -1e30f, m1 = -1e30f;
        #pragma unroll
        for (int nt = 0; nt < 16; nt++) {
            const int cw = (nt * 8 + 2 * fc) >> 1;
            const float2 k0 = ubf2(mr0[cw]);
            const float2 k1 = ubf2(mr1[cw]);
            s[nt][0] *= k0.x; s[nt][1] *= k0.y;
            s[nt][2] *= k1.x; s[nt][3] *= k1.y;
            m0 = fmaxf(m0, fmaxf(s[nt][0], s[nt][1]));
            m1 = fmaxf(m1, fmaxf(s[nt][2], s[nt][3]));
        }
        m0 = fmaxf(m0, __shfl_xor_sync(0xffffffffu, m0, 1));
        m0 = fmaxf(m0, __shfl_xor_sync(0xffffffffu, m0, 2));
        m1 = fmaxf(m1, __shfl_xor_sync(0xffffffffu, m1, 1));
        m1 = fmaxf(m1, __shfl_xor_sync(0xffffffffu, m1, 2));

        const float mn0 = fmaxf(rm0, m0);
        const float mn1 = fmaxf(rm1, m1);
        const float al0 = ex2f(rm0 - mn0);
        const float al1 = ex2f(rm1 - mn1);
        rm0 = mn0; rm1 = mn1;

        #pragma unroll
        for (int nt = 0; nt < 8; nt++) {
            acc_o[nt][0] *= al0; acc_o[nt][1] *= al0;
            acc_o[nt][2] *= al1; acc_o[nt][3] *= al1;
        }

        // ---- p = exp2(s - m) via MUFU, stage P, row sums ----
        float s0 = 0.0f, s1 = 0.0f;
        #pragma unroll
        for (int nt = 0; nt < 16; nt++) {
            const float p0 = ex2f(s[nt][0] - mn0);
            const float p1 = ex2f(s[nt][1] - mn0);
            const float p2 = ex2f(s[nt][2] - mn1);
            const float p3 = ex2f(s[nt][3] - mn1);
            s0 += p0 + p1; s1 += p2 + p3;
            Ps[prow0 + nt * 4 + fc] = bf2(p0, p1);
            Ps[prow1 + nt * 4 + fc] = bf2(p2, p3);
        }
        s0 += __shfl_xor_sync(0xffffffffu, s0, 1);
        s0 += __shfl_xor_sync(0xffffffffu, s0, 2);
        s1 += __shfl_xor_sync(0xffffffffu, s1, 1);
        s1 += __shfl_xor_sync(0xffffffffu, s1, 2);
        rl0 = rl0 * al0 + s0;
        rl1 = rl1 * al1 + s1;

        __syncwarp();   // Ps visible to warp

        // ---- PV: acc_o += P @ V (Vt layout: 1 u32 LDS per b reg) ----
        #pragma unroll
        for (int ks = 0; ks < 8; ks++) {
            uint32_t a[4];
            const int base = prow0 + ks * 8 + fc;
            a[0] = Ps[base];
            a[1] = Ps[base + 8 * FP_STR];
            a[2] = Ps[base + 4];
            a[3] = Ps[base + 8 * FP_STR + 4];
            #pragma unroll
            for (int nt = 0; nt < 8; nt++) {
                const int row = (nt * 8 + fr) * VT_STR;
                uint32_t bv_[2];
                bv_[0] = Vt[row + ks * 8 + fc];
                bv_[1] = Vt[row + ks * 8 + fc + 4];
                mma16(acc_o[nt], a, bv_);
            }
        }
    }

    // ---- normalize and write (bf16) ----
    {
        const int r0 = warp * 16 + fr;
        const float i0 = 1.0f / rl0;
        const float i1 = 1.0f / rl1;
        #pragma unroll
        for (int nt = 0; nt < 8; nt++) {
            const int c = nt * 8 + 2 * fc;
            *(uint32_t*)&Aout[(tb + q0 + r0) * HIDN + h * 64 + c] =
                bf2(acc_o[nt][0] * i0, acc_o[nt][1] * i0);
            *(uint32_t*)&Aout[(tb + q0 + r0 + 8) * HIDN + h * 64 + c] =
                bf2(acc_o[nt][2] * i1, acc_o[nt][3] * i1);
        }
    }
}

// ---------------------------------------------------------------------------
// launch
// ---------------------------------------------------------------------------
extern "C" void kernel_launch(void* const* d_in, const int* in_sizes, int n_in,
                              void* d_out, int out_size)
{
    (void)in_sizes; (void)n_in; (void)out_size;
    const float* x    = (const float*)d_in[0];
    const float* mask = (const float*)d_in[1];
    const float* Wq   = (const float*)d_in[2];
    const float* bq   = (const float*)d_in[3];
    const float* Wk   = (const float*)d_in[4];
    const float* bk   = (const float*)d_in[5];
    const float* Wv   = (const float*)d_in[6];
    const float* bv   = (const float*)d_in[7];
    const float* Wo   = (const float*)d_in[8];
    const float* bo   = (const float*)d_in[9];
    float* out = (float*)d_out;

    __nv_bfloat16 *xb, *mb, *WqT, *WkT, *WvT, *WoT, *Qb, *Kb, *Vb, *Ab;
    cudaGetSymbolAddress((void**)&xb,  g_xb);
    cudaGetSymbolAddress((void**)&mb,  g_mb);
    cudaGetSymbolAddress((void**)&WqT, g_WqT);
    cudaGetSymbolAddress((void**)&WkT, g_WkT);
    cudaGetSymbolAddress((void**)&WvT, g_WvT);
    cudaGetSymbolAddress((void**)&WoT, g_WoT);
    cudaGetSymbolAddress((void**)&Qb,  g_Qb);
    cudaGetSymbolAddress((void**)&Kb,  g_Kb);
    cudaGetSymbolAddress((void**)&Vb,  g_Vb);
    cudaGetSymbolAddress((void**)&Ab,  g_Ab);

    cudaFuncSetAttribute(fa_kernel, cudaFuncAttributeMaxDynamicSharedMemorySize, FA_SMEM);
    cudaFuncSetAttribute(qkv_gemm_kernel, cudaFuncAttributeMaxDynamicSharedMemorySize, G_SMEM);
    cudaFuncSetAttribute(o_gemm_kernel, cudaFuncAttributeMaxDynamicSharedMemorySize, G_SMEM);

    // fused prep: x/mask bf16 conversion + all 4 weight transposes
    prep_kernel<<<5632, 256>>>(x, xb, mask, mb,
                               Wq, WqT, Wk, WkT, Wv, WvT, Wo, WoT);

    // fused Q/K/V projections (bf16 NT)
    qkv_gemm_kernel<<<dim3(24, 16), 256, G_SMEM>>>(xb, WqT, bq, Qb,
                                                   WkT, bk, Kb, WvT, bv, Vb);
    // fused attention (MUFU softmax, bf16 mask)
    fa_kernel<<<dim3(8, 64), 256, FA_SMEM>>>(Qb, Kb, Vb, mb, Ab);
    // output projection + bias + residual
    o_gemm_kernel<<<dim3(16, 16), 256, G_SMEM>>>(Ab, WoT, bo, out, x);
}